// round 1
// baseline (speedup 1.0000x reference)
#include <cuda_runtime.h>
#include <cstdint>

typedef unsigned long long u64;

// ---- packed f32x2 helpers (sm_100+ PTX) -----------------------------------
__device__ __forceinline__ u64 pk2(float a, float b) {
    u64 r; asm("mov.b64 %0, {%1,%2};" : "=l"(r) : "f"(a), "f"(b)); return r;
}
__device__ __forceinline__ void up2(u64 v, float& a, float& b) {
    asm("mov.b64 {%0,%1}, %2;" : "=f"(a), "=f"(b) : "l"(v));
}
__device__ __forceinline__ u64 fma2(u64 a, u64 b, u64 c) {
    u64 d; asm("fma.rn.f32x2 %0, %1, %2, %3;" : "=l"(d) : "l"(a), "l"(b), "l"(c)); return d;
}
__device__ __forceinline__ u64 add2(u64 a, u64 b) {
    u64 d; asm("add.rn.f32x2 %0, %1, %2;" : "=l"(d) : "l"(a), "l"(b)); return d;
}

// ---- problem constants -----------------------------------------------------
constexpr int D    = 64;
constexpr int M    = 2048;
constexpr int K    = 8;
constexpr int NTOK = 16 * 2048;      // B*S = 32768
constexpr int CB   = 32;             // codes staged per tile
constexpr int NTILES = M / CB;       // 64
constexpr int NT   = 64;             // threads per CTA
constexpr int TPC  = 2 * NT;         // tokens per CTA = 128
constexpr int NCTA = NTOK / TPC;     // 256

// Each thread owns 2 tokens packed into f32x2 lanes (lo = tok0, hi = tok1).
// Numerics replicate the reference exactly (given matching XLA summation order):
//   cross = ascending-d fp32 FMA chain
//   r2    = ascending-d fp32 FMA chain over residual
//   d2    = fl(fl(r2 - 2*cross) + c2)   (product 2*cross exact; FMA(-2,cross,r2)
//           rounds identically to the subtract)
//   argmin: strict < scanning ascending code index (first-min tie rule)
//   residual -= code, quantized = x - residual: exact elementwise fp32 ops.
__global__ void __launch_bounds__(NT)
rvq_kernel(const float* __restrict__ x, const float* __restrict__ cb,
           float* __restrict__ qout, float* __restrict__ idxout)
{
    // duplicated {c,c} per dim; row stride 66 (528B = 33*16B: 16B-aligned rows,
    // staging STS conflicts reduced to 4-way)
    __shared__ __align__(16) u64 shc[CB][D + 2];
    __shared__ float c2p[2][CB];

    const int t    = threadIdx.x;
    const int base = blockIdx.x * TPC;
    const int tok0 = base + t;
    const int tok1 = base + NT + t;

    const float4* xa = reinterpret_cast<const float4*>(x + (size_t)tok0 * D);
    const float4* xb = reinterpret_cast<const float4*>(x + (size_t)tok1 * D);

    u64 res[D];
    #pragma unroll
    for (int i = 0; i < 16; i++) {
        float4 a = xa[i], b = xb[i];
        res[4*i+0] = pk2(a.x, b.x); res[4*i+1] = pk2(a.y, b.y);
        res[4*i+2] = pk2(a.z, b.z); res[4*i+3] = pk2(a.w, b.w);
    }

    const u64 NEG1 = pk2(-1.0f, -1.0f);
    const u64 NEG2 = pk2(-2.0f, -2.0f);

    const int sj = t & 31;   // staged code within tile
    const int sp = t >> 5;   // dim half (0: dims 0..31, 1: dims 32..63)

    for (int k = 0; k < K; k++) {
        // token norms: ascending-d FMA chain, both tokens in one packed chain
        u64 n2 = 0ull;
        #pragma unroll
        for (int d = 0; d < D; d++) n2 = fma2(res[d], res[d], n2);

        float m0 = 3.402823466e38f, m1 = 3.402823466e38f;
        int   i0 = 0, i1 = 0;
        const float* cbk = cb + (size_t)k * M * D;

        for (int tile = 0; tile < NTILES; tile++) {
            __syncthreads();   // previous tile fully consumed
            // ---- stage 32 codes (64 threads: one half-row each) ----
            {
                const float4* src = reinterpret_cast<const float4*>(
                    cbk + (size_t)(tile * CB + sj) * D + sp * 32);
                float c2 = 0.0f;
                #pragma unroll
                for (int i = 0; i < 8; i++) {
                    float4 v = src[i];
                    int dd = sp * 32 + 4 * i;
                    shc[sj][dd+0] = pk2(v.x, v.x);
                    shc[sj][dd+1] = pk2(v.y, v.y);
                    shc[sj][dd+2] = pk2(v.z, v.z);
                    shc[sj][dd+3] = pk2(v.w, v.w);
                    c2 = fmaf(v.x, v.x, c2); c2 = fmaf(v.y, v.y, c2);
                    c2 = fmaf(v.z, v.z, c2); c2 = fmaf(v.w, v.w, c2);
                }
                c2p[sp][sj] = c2;
            }
            __syncthreads();

            // ---- scan 32 codes, 4 at a time (ILP-4 FMA2 chains) ----
            #pragma unroll 1
            for (int j = 0; j < CB; j += 4) {
                const u64* p0 = &shc[j+0][0];
                const u64* p1 = &shc[j+1][0];
                const u64* p2 = &shc[j+2][0];
                const u64* p3 = &shc[j+3][0];
                u64 a0 = 0ull, a1 = 0ull, a2 = 0ull, a3 = 0ull;
                #pragma unroll
                for (int d = 0; d < D; d += 2) {
                    ulonglong2 v0 = *reinterpret_cast<const ulonglong2*>(p0 + d);
                    ulonglong2 v1 = *reinterpret_cast<const ulonglong2*>(p1 + d);
                    ulonglong2 v2 = *reinterpret_cast<const ulonglong2*>(p2 + d);
                    ulonglong2 v3 = *reinterpret_cast<const ulonglong2*>(p3 + d);
                    a0 = fma2(res[d], v0.x, a0); a0 = fma2(res[d+1], v0.y, a0);
                    a1 = fma2(res[d], v1.x, a1); a1 = fma2(res[d+1], v1.y, a1);
                    a2 = fma2(res[d], v2.x, a2); a2 = fma2(res[d+1], v2.y, a2);
                    a3 = fma2(res[d], v3.x, a3); a3 = fma2(res[d+1], v3.y, a3);
                }
                const int jb = tile * CB + j;
                float c2a = c2p[0][j+0] + c2p[1][j+0];
                float c2b = c2p[0][j+1] + c2p[1][j+1];
                float c2c = c2p[0][j+2] + c2p[1][j+2];
                float c2d = c2p[0][j+3] + c2p[1][j+3];
                u64 d0 = add2(fma2(a0, NEG2, n2), pk2(c2a, c2a));
                u64 d1 = add2(fma2(a1, NEG2, n2), pk2(c2b, c2b));
                u64 d2 = add2(fma2(a2, NEG2, n2), pk2(c2c, c2c));
                u64 d3 = add2(fma2(a3, NEG2, n2), pk2(c2d, c2d));
                float lo, hi;
                up2(d0, lo, hi); if (lo < m0) { m0 = lo; i0 = jb+0; } if (hi < m1) { m1 = hi; i1 = jb+0; }
                up2(d1, lo, hi); if (lo < m0) { m0 = lo; i0 = jb+1; } if (hi < m1) { m1 = hi; i1 = jb+1; }
                up2(d2, lo, hi); if (lo < m0) { m0 = lo; i0 = jb+2; } if (hi < m1) { m1 = hi; i1 = jb+2; }
                up2(d3, lo, hi); if (lo < m0) { m0 = lo; i0 = jb+3; } if (hi < m1) { m1 = hi; i1 = jb+3; }
            }
        }

        // indices out: shape (K, B, S) -> k*NTOK + token, written as float
        if (idxout) {
            idxout[(size_t)k * NTOK + tok0] = (float)i0;
            idxout[(size_t)k * NTOK + tok1] = (float)i1;
        }

        // residual -= chosen code (fma(-1*c + r) rounds identically to r - c)
        const float4* ca = reinterpret_cast<const float4*>(cbk + (size_t)i0 * D);
        const float4* cw = reinterpret_cast<const float4*>(cbk + (size_t)i1 * D);
        #pragma unroll
        for (int i = 0; i < 16; i++) {
            float4 u = ca[i], w = cw[i];
            res[4*i+0] = fma2(pk2(u.x, w.x), NEG1, res[4*i+0]);
            res[4*i+1] = fma2(pk2(u.y, w.y), NEG1, res[4*i+1]);
            res[4*i+2] = fma2(pk2(u.z, w.z), NEG1, res[4*i+2]);
            res[4*i+3] = fma2(pk2(u.w, w.w), NEG1, res[4*i+3]);
        }
    }

    // quantized = x - residual (exact elementwise, matches reference)
    float4* qa = reinterpret_cast<float4*>(qout + (size_t)tok0 * D);
    float4* qb = reinterpret_cast<float4*>(qout + (size_t)tok1 * D);
    #pragma unroll
    for (int i = 0; i < 16; i++) {
        float4 a = xa[i], b = xb[i];
        float lo, hi; float4 oa, ob;
        up2(res[4*i+0], lo, hi); oa.x = a.x - lo; ob.x = b.x - hi;
        up2(res[4*i+1], lo, hi); oa.y = a.y - lo; ob.y = b.y - hi;
        up2(res[4*i+2], lo, hi); oa.z = a.z - lo; ob.z = b.z - hi;
        up2(res[4*i+3], lo, hi); oa.w = a.w - lo; ob.w = b.w - hi;
        qa[i] = oa; qb[i] = ob;
    }
}

extern "C" void kernel_launch(void* const* d_in, const int* in_sizes, int n_in,
                              void* d_out, int out_size)
{
    const float* x  = (const float*)d_in[0];
    const float* cb = (const float*)d_in[1];
    // defensive: identify tensors by element count (x: 2097152, codebooks: 1048576)
    if (n_in >= 2 && in_sizes[0] == K * M * D && in_sizes[1] == NTOK * D) {
        x  = (const float*)d_in[1];
        cb = (const float*)d_in[0];
    }
    float* q = (float*)d_out;
    // output layout guess: quantized (B,S,D) f32 then indices (K,B,S) as f32
    float* idxf = (out_size >= NTOK * D + K * NTOK) ? (q + (size_t)NTOK * D) : nullptr;

    rvq_kernel<<<NCTA, NT>>>(x, cb, q, idxf);
}

// round 2
// speedup vs baseline: 1.8784x; 1.8784x over previous
#include <cuda_runtime.h>
#include <cstdint>

typedef unsigned long long u64;

// ---- packed f32x2 helpers (sm_100+ PTX) -----------------------------------
__device__ __forceinline__ u64 pk2(float a, float b) {
    u64 r; asm("mov.b64 %0, {%1,%2};" : "=l"(r) : "f"(a), "f"(b)); return r;
}
__device__ __forceinline__ void up2(u64 v, float& a, float& b) {
    asm("mov.b64 {%0,%1}, %2;" : "=f"(a), "=f"(b) : "l"(v));
}
__device__ __forceinline__ u64 fma2(u64 a, u64 b, u64 c) {
    u64 d; asm("fma.rn.f32x2 %0, %1, %2, %3;" : "=l"(d) : "l"(a), "l"(b), "l"(c)); return d;
}
__device__ __forceinline__ u64 add2(u64 a, u64 b) {
    u64 d; asm("add.rn.f32x2 %0, %1, %2;" : "=l"(d) : "l"(a), "l"(b)); return d;
}

// ---- problem constants -----------------------------------------------------
constexpr int D     = 64;
constexpr int M     = 2048;
constexpr int K     = 8;
constexpr int NTOK  = 16 * 2048;     // B*S = 32768
constexpr int R     = 4;             // replica warps (codebook split)
constexpr int MR    = M / R;         // 512 codes per replica
constexpr int CB    = 16;            // codes staged per warp-private tile
constexpr int NTILES= MR / CB;       // 32
constexpr int NT    = 32 * R;        // 128 threads per CTA
constexpr int PAIRS = 32;            // token-pairs per CTA (one warp-width)
constexpr int TPC   = 2 * PAIRS;     // 64 tokens per CTA
constexpr int NCTA  = NTOK / TPC;    // 512

// Each lane owns 2 tokens packed into f32x2 (lo = tok0, hi = tok1); the R
// warps of a CTA are replicas scanning disjoint code ranges for the SAME 32
// token-pairs. Numerics replicate the reference bit-for-bit (verified
// rel_err = 0.0 in R1):
//   cross: ascending-d fp32 FMA chain
//   r2:    ascending-d fp32 FMA chain over residual
//   d2 = fl(fl(r2 - 2*cross) + c2); c2 rounding proven irrelevant
//   argmin: strict < ascending within replica; lexicographic (d2, idx) merge
//           across replicas == global first-min rule
__global__ void __launch_bounds__(NT, 2)
rvq_kernel(const float* __restrict__ x, const float* __restrict__ cb,
           float* __restrict__ qout, float* __restrict__ idxout)
{
    // warp-private duplicated {c,c} tiles; row stride 66 u64 (528B) keeps
    // 16B alignment and bounds STS conflicts at 4-way
    __shared__ __align__(16) u64 shc[R][CB][D + 2];
    __shared__ float c2h[R][2][CB];
    __shared__ float4 sred[R][PAIRS];   // {m0, bits(i0), m1, bits(i1)}

    const int t    = threadIdx.x;
    const int rep  = t >> 5;
    const int lane = t & 31;
    const int base = blockIdx.x * TPC;
    const int tok0 = base + lane;
    const int tok1 = tok0 + PAIRS;

    const float4* xa = reinterpret_cast<const float4*>(x + (size_t)tok0 * D);
    const float4* xb = reinterpret_cast<const float4*>(x + (size_t)tok1 * D);

    u64 res[D];
    #pragma unroll
    for (int i = 0; i < 16; i++) {
        float4 a = xa[i], b = xb[i];
        res[4*i+0] = pk2(a.x, b.x); res[4*i+1] = pk2(a.y, b.y);
        res[4*i+2] = pk2(a.z, b.z); res[4*i+3] = pk2(a.w, b.w);
    }

    const u64 NEG1 = pk2(-1.0f, -1.0f);
    const u64 NEG2 = pk2(-2.0f, -2.0f);

    const int sj = lane & 15;   // staged code within tile
    const int sp = lane >> 4;   // dim half

    for (int k = 0; k < K; k++) {
        // token norms: ascending-d packed FMA chain (identical in all reps)
        u64 n2 = 0ull;
        #pragma unroll
        for (int d = 0; d < D; d++) n2 = fma2(res[d], res[d], n2);

        float m0 = 3.402823466e38f, m1 = 3.402823466e38f;
        int   i0 = 0, i1 = 0;
        const float* cbk  = cb + (size_t)k * M * D;
        const float* cbr  = cbk + (size_t)rep * MR * D;
        const int    ibase= rep * MR;

        for (int tile = 0; tile < NTILES; tile++) {
            __syncwarp();   // previous warp-private tile fully consumed
            // ---- stage 16 codes (32 lanes: one half-row each) ----
            {
                const float4* src = reinterpret_cast<const float4*>(
                    cbr + (size_t)(tile * CB + sj) * D + sp * 32);
                float c2 = 0.0f;
                #pragma unroll
                for (int i = 0; i < 8; i++) {
                    float4 v = src[i];
                    int dd = sp * 32 + 4 * i;
                    shc[rep][sj][dd+0] = pk2(v.x, v.x);
                    shc[rep][sj][dd+1] = pk2(v.y, v.y);
                    shc[rep][sj][dd+2] = pk2(v.z, v.z);
                    shc[rep][sj][dd+3] = pk2(v.w, v.w);
                    c2 = fmaf(v.x, v.x, c2); c2 = fmaf(v.y, v.y, c2);
                    c2 = fmaf(v.z, v.z, c2); c2 = fmaf(v.w, v.w, c2);
                }
                c2h[rep][sp][sj] = c2;
            }
            __syncwarp();

            // ---- scan 16 codes, 4 at a time (ILP-4 FMA2 chains) ----
            #pragma unroll 1
            for (int j = 0; j < CB; j += 4) {
                const u64* p0 = &shc[rep][j+0][0];
                const u64* p1 = &shc[rep][j+1][0];
                const u64* p2 = &shc[rep][j+2][0];
                const u64* p3 = &shc[rep][j+3][0];
                u64 a0 = 0ull, a1 = 0ull, a2 = 0ull, a3 = 0ull;
                #pragma unroll
                for (int d = 0; d < D; d += 2) {
                    ulonglong2 v0 = *reinterpret_cast<const ulonglong2*>(p0 + d);
                    ulonglong2 v1 = *reinterpret_cast<const ulonglong2*>(p1 + d);
                    ulonglong2 v2 = *reinterpret_cast<const ulonglong2*>(p2 + d);
                    ulonglong2 v3 = *reinterpret_cast<const ulonglong2*>(p3 + d);
                    a0 = fma2(res[d], v0.x, a0); a0 = fma2(res[d+1], v0.y, a0);
                    a1 = fma2(res[d], v1.x, a1); a1 = fma2(res[d+1], v1.y, a1);
                    a2 = fma2(res[d], v2.x, a2); a2 = fma2(res[d+1], v2.y, a2);
                    a3 = fma2(res[d], v3.x, a3); a3 = fma2(res[d+1], v3.y, a3);
                }
                const int jb = ibase + tile * CB + j;
                float c2a = c2h[rep][0][j+0] + c2h[rep][1][j+0];
                float c2b = c2h[rep][0][j+1] + c2h[rep][1][j+1];
                float c2c = c2h[rep][0][j+2] + c2h[rep][1][j+2];
                float c2d = c2h[rep][0][j+3] + c2h[rep][1][j+3];
                u64 d0 = add2(fma2(a0, NEG2, n2), pk2(c2a, c2a));
                u64 d1 = add2(fma2(a1, NEG2, n2), pk2(c2b, c2b));
                u64 d2 = add2(fma2(a2, NEG2, n2), pk2(c2c, c2c));
                u64 d3 = add2(fma2(a3, NEG2, n2), pk2(c2d, c2d));
                float lo, hi;
                up2(d0, lo, hi); if (lo < m0) { m0 = lo; i0 = jb+0; } if (hi < m1) { m1 = hi; i1 = jb+0; }
                up2(d1, lo, hi); if (lo < m0) { m0 = lo; i0 = jb+1; } if (hi < m1) { m1 = hi; i1 = jb+1; }
                up2(d2, lo, hi); if (lo < m0) { m0 = lo; i0 = jb+2; } if (hi < m1) { m1 = hi; i1 = jb+2; }
                up2(d3, lo, hi); if (lo < m0) { m0 = lo; i0 = jb+3; } if (hi < m1) { m1 = hi; i1 = jb+3; }
            }
        }

        // ---- merge argmin across the R replicas (lexicographic on (m, i)) ----
        sred[rep][lane] = make_float4(m0, __int_as_float(i0), m1, __int_as_float(i1));
        __syncthreads();
        float gm0 = 3.402823466e38f, gm1 = 3.402823466e38f;
        int   gi0 = 0, gi1 = 0;
        #pragma unroll
        for (int r = 0; r < R; r++) {
            float4 v = sred[r][lane];
            float rm0 = v.x, rm1 = v.z;
            int   ri0 = __float_as_int(v.y), ri1 = __float_as_int(v.w);
            if (rm0 < gm0 || (rm0 == gm0 && ri0 < gi0)) { gm0 = rm0; gi0 = ri0; }
            if (rm1 < gm1 || (rm1 == gm1 && ri1 < gi1)) { gm1 = rm1; gi1 = ri1; }
        }
        __syncthreads();   // sred reusable next k

        // indices out: (K, B, S), written as float — only replica 0
        if (rep == 0 && idxout) {
            idxout[(size_t)k * NTOK + tok0] = (float)gi0;
            idxout[(size_t)k * NTOK + tok1] = (float)gi1;
        }

        // residual -= chosen code (every replica updates its own copy)
        const float4* ca = reinterpret_cast<const float4*>(cbk + (size_t)gi0 * D);
        const float4* cw = reinterpret_cast<const float4*>(cbk + (size_t)gi1 * D);
        #pragma unroll
        for (int i = 0; i < 16; i++) {
            float4 u = ca[i], w = cw[i];
            res[4*i+0] = fma2(pk2(u.x, w.x), NEG1, res[4*i+0]);
            res[4*i+1] = fma2(pk2(u.y, w.y), NEG1, res[4*i+1]);
            res[4*i+2] = fma2(pk2(u.z, w.z), NEG1, res[4*i+2]);
            res[4*i+3] = fma2(pk2(u.w, w.w), NEG1, res[4*i+3]);
        }
    }

    // quantized = x - residual (exact elementwise) — replica 0 only
    if (rep == 0) {
        float4* qa = reinterpret_cast<float4*>(qout + (size_t)tok0 * D);
        float4* qb = reinterpret_cast<float4*>(qout + (size_t)tok1 * D);
        #pragma unroll
        for (int i = 0; i < 16; i++) {
            float4 a = xa[i], b = xb[i];
            float lo, hi; float4 oa, ob;
            up2(res[4*i+0], lo, hi); oa.x = a.x - lo; ob.x = b.x - hi;
            up2(res[4*i+1], lo, hi); oa.y = a.y - lo; ob.y = b.y - hi;
            up2(res[4*i+2], lo, hi); oa.z = a.z - lo; ob.z = b.z - hi;
            up2(res[4*i+3], lo, hi); oa.w = a.w - lo; ob.w = b.w - hi;
            qa[i] = oa; qb[i] = ob;
        }
    }
}

extern "C" void kernel_launch(void* const* d_in, const int* in_sizes, int n_in,
                              void* d_out, int out_size)
{
    const float* x  = (const float*)d_in[0];
    const float* cb = (const float*)d_in[1];
    if (n_in >= 2 && in_sizes[0] == K * M * D && in_sizes[1] == NTOK * D) {
        x  = (const float*)d_in[1];
        cb = (const float*)d_in[0];
    }
    float* q = (float*)d_out;
    float* idxf = (out_size >= NTOK * D + K * NTOK) ? (q + (size_t)NTOK * D) : nullptr;

    rvq_kernel<<<NCTA, NT>>>(x, cb, q, idxf);
}

// round 3
// speedup vs baseline: 3.4091x; 1.8149x over previous
#include <cuda_runtime.h>
#include <cstdint>

typedef unsigned long long u64;

// ---- packed f32x2 helpers --------------------------------------------------
__device__ __forceinline__ u64 pk2(float a, float b) {
    u64 r; asm("mov.b64 %0, {%1,%2};" : "=l"(r) : "f"(a), "f"(b)); return r;
}
__device__ __forceinline__ void up2(u64 v, float& a, float& b) {
    asm("mov.b64 {%0,%1}, %2;" : "=f"(a), "=f"(b) : "l"(v));
}
__device__ __forceinline__ u64 fma2(u64 a, u64 b, u64 c) {
    u64 d; asm("fma.rn.f32x2 %0, %1, %2, %3;" : "=l"(d) : "l"(a), "l"(b), "l"(c)); return d;
}
__device__ __forceinline__ u64 add2(u64 a, u64 b) {
    u64 d; asm("add.rn.f32x2 %0, %1, %2;" : "=l"(d) : "l"(a), "l"(b)); return d;
}

// ---- problem constants -----------------------------------------------------
constexpr int D      = 64;
constexpr int M      = 2048;
constexpr int K      = 8;
constexpr int NTOK   = 32768;      // B*S
constexpr int TPC    = 64;         // tokens per CTA
constexpr int PAIRS  = 32;         // token pairs per CTA (tok p, tok p+32)
constexpr int C      = 64;         // codes per staged tile
constexpr int NTILES = M / C;      // 32
constexpr int NT     = 128;        // threads per CTA
constexpr int NCTA   = NTOK / TPC; // 512

// ---- dynamic smem layout (bytes) -------------------------------------------
constexpr int OFF_RP  = 0;                       // u64 RP[D][PAIRS]      16 KB
constexpr int OFF_CP  = OFF_RP + D * PAIRS * 8;  // u64 CP[D][C]          32 KB
constexpr int OFF_C2  = OFF_CP + D * C * 8;      // float C2[2][C]        512 B
constexpr int OFF_R2  = OFF_C2 + 2 * C * 4;      // u64 R2s[PAIRS]        256 B
constexpr int OFF_CHO = OFF_R2 + PAIRS * 8;      // int2 CHO[PAIRS]       256 B
constexpr int SMEMB   = OFF_CHO + PAIRS * 8;     // 50176 B
constexpr int OFF_MIN = OFF_CP;                  // float4 MN[16][8][4] aliases CP (8 KB)

// Register-blocked smem GEMM: 128 threads; thread (pr = t&7, cg = t>>3) owns
// pairs {pr, pr+8, pr+16, pr+24} x codes {4cg..4cg+3} -> 16 FMA2 accumulators.
// Numerics replicate the reference bit-for-bit (rel_err 0.0 in R1/R2):
// ascending-d FMA chains for cross/r2; d2 = (r2 - 2*cross) + c2 with c2 =
// half-chain sums; strict-< ascending argmin + lexicographic (d2, idx) merge.
__global__ void __launch_bounds__(NT, 4)
rvq_kernel(const float* __restrict__ x, const float* __restrict__ cb,
           float* __restrict__ qout, float* __restrict__ idxout)
{
    extern __shared__ __align__(16) char sm[];
    u64*    RP  = (u64*)(sm + OFF_RP);
    u64*    CP  = (u64*)(sm + OFF_CP);
    float*  C2  = (float*)(sm + OFF_C2);
    u64*    R2s = (u64*)(sm + OFF_R2);
    int2*   CHO = (int2*)(sm + OFF_CHO);
    float4* MN  = (float4*)(sm + OFF_MIN);

    const int t    = threadIdx.x;
    const int base = blockIdx.x * TPC;
    const int pr   = t & 7;          // pair stripe
    const int cg   = t >> 3;         // code group (0..15)
    const int pq   = t & 31;         // pair for init/update/output roles
    const int qh   = t >> 5;         // dim quarter (0..3)
    const int tok0 = base + pq;
    const int tok1 = tok0 + PAIRS;

    const u64 NEG1 = pk2(-1.0f, -1.0f);
    const u64 NEG2 = pk2(-2.0f, -2.0f);

    // ---- init: pack x into RP (pair p = tokens p, p+32) ----
    {
        const float4* xa = (const float4*)(x + (size_t)tok0 * D) + qh * 4;
        const float4* xb = (const float4*)(x + (size_t)tok1 * D) + qh * 4;
        #pragma unroll
        for (int i = 0; i < 4; i++) {
            float4 a = xa[i], b = xb[i];
            int d = qh * 16 + i * 4;
            RP[(d+0)*PAIRS + pq] = pk2(a.x, b.x);
            RP[(d+1)*PAIRS + pq] = pk2(a.y, b.y);
            RP[(d+2)*PAIRS + pq] = pk2(a.z, b.z);
            RP[(d+3)*PAIRS + pq] = pk2(a.w, b.w);
        }
    }
    __syncthreads();

    const int sc = t & 63;   // staging: code within tile
    const int sh = t >> 6;   // staging: dim half

    for (int k = 0; k < K; k++) {
        const float* cbk = cb + (size_t)k * M * D;

        // ---- r2 per pair: ascending-d packed FMA chain ----
        if (t < PAIRS) {
            u64 n2 = 0ull;
            #pragma unroll 8
            for (int d = 0; d < D; d++) { u64 v = RP[d*PAIRS + t]; n2 = fma2(v, v, n2); }
            R2s[t] = n2;
        }
        __syncthreads();

        u64 r2p0 = R2s[pr], r2p1 = R2s[pr+8], r2p2 = R2s[pr+16], r2p3 = R2s[pr+24];

        float mlo0 = 3.402823466e38f, mlo1 = mlo0, mlo2 = mlo0, mlo3 = mlo0;
        float mhi0 = mlo0, mhi1 = mlo0, mhi2 = mlo0, mhi3 = mlo0;
        int   il0 = 0, il1 = 0, il2 = 0, il3 = 0;
        int   ih0 = 0, ih1 = 0, ih2 = 0, ih3 = 0;

        for (int tile = 0; tile < NTILES; tile++) {
            // ---- stage 64 codes: dup {c,c}; c2 as two ascending half-chains ----
            {
                const float4* src = (const float4*)(cbk + (size_t)(tile*C + sc) * D + sh * 32);
                float c2 = 0.0f;
                #pragma unroll
                for (int i = 0; i < 8; i++) {
                    float4 v = src[i];
                    int d = sh * 32 + i * 4;
                    CP[(d+0)*C + sc] = pk2(v.x, v.x);
                    CP[(d+1)*C + sc] = pk2(v.y, v.y);
                    CP[(d+2)*C + sc] = pk2(v.z, v.z);
                    CP[(d+3)*C + sc] = pk2(v.w, v.w);
                    c2 = fmaf(v.x, v.x, c2); c2 = fmaf(v.y, v.y, c2);
                    c2 = fmaf(v.z, v.z, c2); c2 = fmaf(v.w, v.w, c2);
                }
                C2[sh * C + sc] = c2;
            }
            __syncthreads();

            // ---- cross: 4 pairs x 4 codes outer product, ascending-d chains ----
            u64 a00=0,a01=0,a02=0,a03=0, a10=0,a11=0,a12=0,a13=0;
            u64 a20=0,a21=0,a22=0,a23=0, a30=0,a31=0,a32=0,a33=0;
            #pragma unroll 8
            for (int d = 0; d < D; d++) {
                const u64* rp = RP + d * PAIRS;
                u64 P0 = rp[pr], P1 = rp[pr+8], P2 = rp[pr+16], P3 = rp[pr+24];
                ulonglong2 cA = *(const ulonglong2*)(CP + d*C + 4*cg);
                ulonglong2 cB = *(const ulonglong2*)(CP + d*C + 4*cg + 2);
                a00 = fma2(P0, cA.x, a00); a01 = fma2(P0, cA.y, a01);
                a02 = fma2(P0, cB.x, a02); a03 = fma2(P0, cB.y, a03);
                a10 = fma2(P1, cA.x, a10); a11 = fma2(P1, cA.y, a11);
                a12 = fma2(P1, cB.x, a12); a13 = fma2(P1, cB.y, a13);
                a20 = fma2(P2, cA.x, a20); a21 = fma2(P2, cA.y, a21);
                a22 = fma2(P2, cB.x, a22); a23 = fma2(P2, cB.y, a23);
                a30 = fma2(P3, cA.x, a30); a31 = fma2(P3, cA.y, a31);
                a32 = fma2(P3, cB.x, a32); a33 = fma2(P3, cB.y, a33);
            }

            // ---- d2 + running argmin (codes ascending j, tiles ascending) ----
            const int jb = tile * C + 4 * cg;
            float c2v0 = C2[4*cg+0] + C2[C + 4*cg+0];
            float c2v1 = C2[4*cg+1] + C2[C + 4*cg+1];
            float c2v2 = C2[4*cg+2] + C2[C + 4*cg+2];
            float c2v3 = C2[4*cg+3] + C2[C + 4*cg+3];
            u64 cd0 = pk2(c2v0, c2v0), cd1 = pk2(c2v1, c2v1);
            u64 cd2 = pk2(c2v2, c2v2), cd3 = pk2(c2v3, c2v3);
            float lo, hi;
            #define EVAL(ACC, R2P, CD, JJ, ML, IL, MH, IH)                         \
                up2(add2(fma2(ACC, NEG2, R2P), CD), lo, hi);                       \
                if (lo < ML) { ML = lo; IL = jb + JJ; }                            \
                if (hi < MH) { MH = hi; IH = jb + JJ; }
            EVAL(a00, r2p0, cd0, 0, mlo0, il0, mhi0, ih0)
            EVAL(a01, r2p0, cd1, 1, mlo0, il0, mhi0, ih0)
            EVAL(a02, r2p0, cd2, 2, mlo0, il0, mhi0, ih0)
            EVAL(a03, r2p0, cd3, 3, mlo0, il0, mhi0, ih0)
            EVAL(a10, r2p1, cd0, 0, mlo1, il1, mhi1, ih1)
            EVAL(a11, r2p1, cd1, 1, mlo1, il1, mhi1, ih1)
            EVAL(a12, r2p1, cd2, 2, mlo1, il1, mhi1, ih1)
            EVAL(a13, r2p1, cd3, 3, mlo1, il1, mhi1, ih1)
            EVAL(a20, r2p2, cd0, 0, mlo2, il2, mhi2, ih2)
            EVAL(a21, r2p2, cd1, 1, mlo2, il2, mhi2, ih2)
            EVAL(a22, r2p2, cd2, 2, mlo2, il2, mhi2, ih2)
            EVAL(a23, r2p2, cd3, 3, mlo2, il2, mhi2, ih2)
            EVAL(a30, r2p3, cd0, 0, mlo3, il3, mhi3, ih3)
            EVAL(a31, r2p3, cd1, 1, mlo3, il3, mhi3, ih3)
            EVAL(a32, r2p3, cd2, 2, mlo3, il3, mhi3, ih3)
            EVAL(a33, r2p3, cd3, 3, mlo3, il3, mhi3, ih3)
            #undef EVAL
            __syncthreads();   // CP fully consumed before next stage / MN alias
        }

        // ---- cross-thread argmin merge (MN aliases CP; safe after sync) ----
        MN[(cg*8 + pr)*4 + 0] = make_float4(mlo0, __int_as_float(il0), mhi0, __int_as_float(ih0));
        MN[(cg*8 + pr)*4 + 1] = make_float4(mlo1, __int_as_float(il1), mhi1, __int_as_float(ih1));
        MN[(cg*8 + pr)*4 + 2] = make_float4(mlo2, __int_as_float(il2), mhi2, __int_as_float(ih2));
        MN[(cg*8 + pr)*4 + 3] = make_float4(mlo3, __int_as_float(il3), mhi3, __int_as_float(ih3));
        __syncthreads();

        if (t < PAIRS) {
            const int p = t, ppr = p & 7, sl = p >> 3;
            float g0 = 3.402823466e38f, g1 = g0;
            int gi0 = 0, gi1 = 0;
            #pragma unroll
            for (int c = 0; c < 16; c++) {
                float4 v = MN[(c*8 + ppr)*4 + sl];
                float va = v.x, vb = v.z;
                int ia = __float_as_int(v.y), ib = __float_as_int(v.w);
                if (va < g0 || (va == g0 && ia < gi0)) { g0 = va; gi0 = ia; }
                if (vb < g1 || (vb == g1 && ib < gi1)) { g1 = vb; gi1 = ib; }
            }
            CHO[p] = make_int2(gi0, gi1);
            if (idxout) {
                idxout[(size_t)k * NTOK + base + p]         = (float)gi0;
                idxout[(size_t)k * NTOK + base + PAIRS + p] = (float)gi1;
            }
        }
        __syncthreads();

        // ---- residual update: RP[d][p] -= code (exact fma(-1,c,r)) ----
        {
            int2 ch = CHO[pq];
            const float4* ca = (const float4*)(cbk + (size_t)ch.x * D) + qh * 4;
            const float4* cw = (const float4*)(cbk + (size_t)ch.y * D) + qh * 4;
            #pragma unroll
            for (int i = 0; i < 4; i++) {
                float4 u = ca[i], w = cw[i];
                int d = qh * 16 + i * 4;
                RP[(d+0)*PAIRS+pq] = fma2(pk2(u.x, w.x), NEG1, RP[(d+0)*PAIRS+pq]);
                RP[(d+1)*PAIRS+pq] = fma2(pk2(u.y, w.y), NEG1, RP[(d+1)*PAIRS+pq]);
                RP[(d+2)*PAIRS+pq] = fma2(pk2(u.z, w.z), NEG1, RP[(d+2)*PAIRS+pq]);
                RP[(d+3)*PAIRS+pq] = fma2(pk2(u.w, w.w), NEG1, RP[(d+3)*PAIRS+pq]);
            }
        }
        __syncthreads();
    }

    // ---- output: quantized = x - residual (exact elementwise) ----
    {
        const float4* xa = (const float4*)(x + (size_t)tok0 * D) + qh * 4;
        const float4* xb = (const float4*)(x + (size_t)tok1 * D) + qh * 4;
        float4* qa = (float4*)(qout + (size_t)tok0 * D) + qh * 4;
        float4* qb = (float4*)(qout + (size_t)tok1 * D) + qh * 4;
        #pragma unroll
        for (int i = 0; i < 4; i++) {
            float4 a = xa[i], b = xb[i];
            float4 oa, ob; float lo, hi;
            int d = qh * 16 + i * 4;
            up2(RP[(d+0)*PAIRS+pq], lo, hi); oa.x = a.x - lo; ob.x = b.x - hi;
            up2(RP[(d+1)*PAIRS+pq], lo, hi); oa.y = a.y - lo; ob.y = b.y - hi;
            up2(RP[(d+2)*PAIRS+pq], lo, hi); oa.z = a.z - lo; ob.z = b.z - hi;
            up2(RP[(d+3)*PAIRS+pq], lo, hi); oa.w = a.w - lo; ob.w = b.w - hi;
            qa[i] = oa; qb[i] = ob;
        }
    }
}

extern "C" void kernel_launch(void* const* d_in, const int* in_sizes, int n_in,
                              void* d_out, int out_size)
{
    const float* x  = (const float*)d_in[0];
    const float* cb = (const float*)d_in[1];
    if (n_in >= 2 && in_sizes[0] == K * M * D && in_sizes[1] == NTOK * D) {
        x  = (const float*)d_in[1];
        cb = (const float*)d_in[0];
    }
    float* q = (float*)d_out;
    float* idxf = (out_size >= NTOK * D + K * NTOK) ? (q + (size_t)NTOK * D) : nullptr;

    cudaFuncSetAttribute(rvq_kernel, cudaFuncAttributeMaxDynamicSharedMemorySize, SMEMB);
    rvq_kernel<<<NCTA, NT, SMEMB>>>(x, cb, q, idxf);
}

// round 4
// speedup vs baseline: 4.0535x; 1.1890x over previous
#include <cuda_runtime.h>
#include <cstdint>

typedef unsigned long long u64;

// ---- packed f32x2 helpers --------------------------------------------------
__device__ __forceinline__ u64 pk2(float a, float b) {
    u64 r; asm("mov.b64 %0, {%1,%2};" : "=l"(r) : "f"(a), "f"(b)); return r;
}
__device__ __forceinline__ void up2(u64 v, float& a, float& b) {
    asm("mov.b64 {%0,%1}, %2;" : "=f"(a), "=f"(b) : "l"(v));
}
__device__ __forceinline__ u64 fma2(u64 a, u64 b, u64 c) {
    u64 d; asm("fma.rn.f32x2 %0, %1, %2, %3;" : "=l"(d) : "l"(a), "l"(b), "l"(c)); return d;
}
__device__ __forceinline__ u64 add2(u64 a, u64 b) {
    u64 d; asm("add.rn.f32x2 %0, %1, %2;" : "=l"(d) : "l"(a), "l"(b)); return d;
}

// ---- problem constants -----------------------------------------------------
constexpr int D      = 64;
constexpr int M      = 2048;
constexpr int K      = 8;
constexpr int NTOK   = 32768;       // B*S
constexpr int PAIRS  = 32;          // token pairs per CTA (tok p, tok p+32)
constexpr int TPC    = 64;          // tokens per CTA
constexpr int CT     = 128;         // codes per staged tile
constexpr int NTILES = M / CT;      // 16
constexpr int NT     = 64;          // threads per CTA (2 warps)
constexpr int NCTA   = NTOK / TPC;  // 512

// ---- dynamic smem layout (bytes) -------------------------------------------
constexpr int OFF_RP  = 0;                        // u64   RP[D][PAIRS]   16384
constexpr int OFF_CP  = OFF_RP + D * PAIRS * 8;   // float CP[D][CT]      32768
constexpr int OFF_C2  = OFF_CP + D * CT * 4;      // float C2[CT]           512
constexpr int OFF_R2  = OFF_C2 + CT * 4;          // u64   R2s[PAIRS]       256
constexpr int OFF_CHO = OFF_R2 + PAIRS * 8;       // int2  CHO[PAIRS]       256
constexpr int SMEMB   = OFF_CHO + PAIRS * 8;      // 50176
constexpr int OFF_MN  = OFF_CP;                   // float4 MN[NT][8] aliases CP

// 64 threads; thread (pb = 2*(t&3), cg = t>>2) owns pairs
// {pb,pb+1, pb+8,pb+9, pb+16,pb+17, pb+24,pb+25} x codes {8cg..8cg+7}
// -> 64 FMA2 accumulators (8x8 register block). CP holds plain floats;
// {c,c} duplication happens in registers (mov.b64). Numerics replicate the
// reference bit-for-bit (rel_err 0.0 in R1-R3): ascending-d FMA chains,
// d2 = (r2 - 2*cross) + c2, c2 = two ascending 32-dim half-chains summed,
// strict-< ascending argmin + lexicographic (d2, idx) cross-thread merge.
__global__ void __launch_bounds__(NT, 4)
rvq_kernel(const float* __restrict__ x, const float* __restrict__ cb,
           float* __restrict__ qout, float* __restrict__ idxout)
{
    extern __shared__ __align__(16) char sm[];
    u64*    RP  = (u64*)(sm + OFF_RP);
    float*  CP  = (float*)(sm + OFF_CP);
    float*  C2  = (float*)(sm + OFF_C2);
    u64*    R2s = (u64*)(sm + OFF_R2);
    int2*   CHO = (int2*)(sm + OFF_CHO);
    float4* MN  = (float4*)(sm + OFF_MN);

    const int t    = threadIdx.x;
    const int base = blockIdx.x * TPC;
    const int pq   = t & 31;        // pair for init/update/output roles
    const int qh   = t >> 5;        // dim half (0..1)
    const int tok0 = base + pq;
    const int tok1 = tok0 + PAIRS;
    const int pb   = (t & 3) * 2;   // pair base (adjacent pair for LDS.128)
    const int cg   = t >> 2;        // code group (0..15)

    const u64 NEG1 = pk2(-1.0f, -1.0f);
    const u64 NEG2 = pk2(-2.0f, -2.0f);

    // ---- init: pack x into RP (pair p = tokens p, p+32) ----
    {
        const float4* xa = (const float4*)(x + (size_t)tok0 * D) + qh * 8;
        const float4* xb = (const float4*)(x + (size_t)tok1 * D) + qh * 8;
        #pragma unroll
        for (int i = 0; i < 8; i++) {
            float4 a = xa[i], b = xb[i];
            int d = qh * 32 + i * 4;
            RP[(d+0)*PAIRS + pq] = pk2(a.x, b.x);
            RP[(d+1)*PAIRS + pq] = pk2(a.y, b.y);
            RP[(d+2)*PAIRS + pq] = pk2(a.z, b.z);
            RP[(d+3)*PAIRS + pq] = pk2(a.w, b.w);
        }
    }
    __syncthreads();

    for (int k = 0; k < K; k++) {
        const float* cbk = cb + (size_t)k * M * D;

        // ---- r2 per pair: ascending-d packed FMA chain ----
        if (t < PAIRS) {
            u64 n2 = 0ull;
            #pragma unroll 8
            for (int d = 0; d < D; d++) { u64 v = RP[d*PAIRS + t]; n2 = fma2(v, v, n2); }
            R2s[t] = n2;
        }

        float mlo[8], mhi[8]; int ilo[8], ihi[8];
        #pragma unroll
        for (int s = 0; s < 8; s++) {
            mlo[s] = 3.402823466e38f; mhi[s] = 3.402823466e38f; ilo[s] = 0; ihi[s] = 0;
        }

        for (int tile = 0; tile < NTILES; tile++) {
            // ---- stage 128 codes as plain float; c2 = two half-chains ----
            {
                const int c0 = tile * CT + 2 * t;
                const float4* s0 = (const float4*)(cbk + (size_t)c0 * D);
                float c2a = 0.0f, c2b = 0.0f, c2c = 0.0f, c2d = 0.0f;
                #pragma unroll
                for (int i = 0; i < 8; i++) {          // code c0, dims 0..31
                    float4 v = s0[i]; int d = 4*i;
                    CP[(d+0)*CT + 2*t] = v.x; CP[(d+1)*CT + 2*t] = v.y;
                    CP[(d+2)*CT + 2*t] = v.z; CP[(d+3)*CT + 2*t] = v.w;
                    c2a = fmaf(v.x,v.x,c2a); c2a = fmaf(v.y,v.y,c2a);
                    c2a = fmaf(v.z,v.z,c2a); c2a = fmaf(v.w,v.w,c2a);
                }
                #pragma unroll
                for (int i = 8; i < 16; i++) {         // code c0, dims 32..63
                    float4 v = s0[i]; int d = 4*i;
                    CP[(d+0)*CT + 2*t] = v.x; CP[(d+1)*CT + 2*t] = v.y;
                    CP[(d+2)*CT + 2*t] = v.z; CP[(d+3)*CT + 2*t] = v.w;
                    c2b = fmaf(v.x,v.x,c2b); c2b = fmaf(v.y,v.y,c2b);
                    c2b = fmaf(v.z,v.z,c2b); c2b = fmaf(v.w,v.w,c2b);
                }
                const float4* s1 = s0 + 16;            // code c0+1
                #pragma unroll
                for (int i = 0; i < 8; i++) {
                    float4 v = s1[i]; int d = 4*i;
                    CP[(d+0)*CT + 2*t+1] = v.x; CP[(d+1)*CT + 2*t+1] = v.y;
                    CP[(d+2)*CT + 2*t+1] = v.z; CP[(d+3)*CT + 2*t+1] = v.w;
                    c2c = fmaf(v.x,v.x,c2c); c2c = fmaf(v.y,v.y,c2c);
                    c2c = fmaf(v.z,v.z,c2c); c2c = fmaf(v.w,v.w,c2c);
                }
                #pragma unroll
                for (int i = 8; i < 16; i++) {
                    float4 v = s1[i]; int d = 4*i;
                    CP[(d+0)*CT + 2*t+1] = v.x; CP[(d+1)*CT + 2*t+1] = v.y;
                    CP[(d+2)*CT + 2*t+1] = v.z; CP[(d+3)*CT + 2*t+1] = v.w;
                    c2d = fmaf(v.x,v.x,c2d); c2d = fmaf(v.y,v.y,c2d);
                    c2d = fmaf(v.z,v.z,c2d); c2d = fmaf(v.w,v.w,c2d);
                }
                C2[2*t]   = c2a + c2b;
                C2[2*t+1] = c2c + c2d;
            }
            __syncthreads();

            // ---- cross: 8 pairs x 8 codes per thread, ascending-d chains ----
            u64 acc[8][8];
            #pragma unroll
            for (int p = 0; p < 8; p++)
                #pragma unroll
                for (int c = 0; c < 8; c++) acc[p][c] = 0ull;

            #pragma unroll 2
            for (int d = 0; d < D; d++) {
                const u64* rp = RP + d * PAIRS;
                ulonglong2 rA = *(const ulonglong2*)(rp + pb);
                ulonglong2 rB = *(const ulonglong2*)(rp + pb + 8);
                ulonglong2 rC = *(const ulonglong2*)(rp + pb + 16);
                ulonglong2 rD = *(const ulonglong2*)(rp + pb + 24);
                const float4* cf = (const float4*)(CP + d*CT + cg*8);
                float4 cA = cf[0], cB = cf[1];
                u64 cc[8];
                cc[0] = pk2(cA.x, cA.x); cc[1] = pk2(cA.y, cA.y);
                cc[2] = pk2(cA.z, cA.z); cc[3] = pk2(cA.w, cA.w);
                cc[4] = pk2(cB.x, cB.x); cc[5] = pk2(cB.y, cB.y);
                cc[6] = pk2(cB.z, cB.z); cc[7] = pk2(cB.w, cB.w);
                u64 rr[8] = {rA.x, rA.y, rB.x, rB.y, rC.x, rC.y, rD.x, rD.y};
                #pragma unroll
                for (int p = 0; p < 8; p++)
                    #pragma unroll
                    for (int c = 0; c < 8; c++)
                        acc[p][c] = fma2(rr[p], cc[c], acc[p][c]);
            }

            // ---- d2 + running argmin (per pair: ascending code order) ----
            u64 r2v[8];
            r2v[0] = R2s[pb];    r2v[1] = R2s[pb+1];
            r2v[2] = R2s[pb+8];  r2v[3] = R2s[pb+9];
            r2v[4] = R2s[pb+16]; r2v[5] = R2s[pb+17];
            r2v[6] = R2s[pb+24]; r2v[7] = R2s[pb+25];
            const int jb = tile * CT + cg * 8;
            #pragma unroll
            for (int c = 0; c < 8; c++) {
                float c2s = C2[cg*8 + c];
                u64 c2dup = pk2(c2s, c2s);
                #pragma unroll
                for (int p = 0; p < 8; p++) {
                    float lo, hi;
                    up2(add2(fma2(acc[p][c], NEG2, r2v[p]), c2dup), lo, hi);
                    if (lo < mlo[p]) { mlo[p] = lo; ilo[p] = jb + c; }
                    if (hi < mhi[p]) { mhi[p] = hi; ihi[p] = jb + c; }
                }
            }
            __syncthreads();   // CP/C2 consumed; safe to restage / alias MN
        }

        // ---- cross-thread argmin merge (MN aliases CP) ----
        #pragma unroll
        for (int s = 0; s < 8; s++)
            MN[t*8 + s] = make_float4(mlo[s], __int_as_float(ilo[s]),
                                      mhi[s], __int_as_float(ihi[s]));
        __syncthreads();

        if (t < PAIRS) {
            const int p = t;
            const int pr2  = (p & 7) >> 1;
            const int slot = (p >> 3) * 2 + (p & 1);
            float g0 = 3.402823466e38f, g1 = g0;
            int gi0 = 0, gi1 = 0;
            #pragma unroll
            for (int c = 0; c < 16; c++) {   // ascending cg = ascending code blocks
                float4 v = MN[(c*4 + pr2)*8 + slot];
                float va = v.x, vb = v.z;
                int ia = __float_as_int(v.y), ib = __float_as_int(v.w);
                if (va < g0 || (va == g0 && ia < gi0)) { g0 = va; gi0 = ia; }
                if (vb < g1 || (vb == g1 && ib < gi1)) { g1 = vb; gi1 = ib; }
            }
            CHO[p] = make_int2(gi0, gi1);
            if (idxout) {
                idxout[(size_t)k * NTOK + base + p]         = (float)gi0;
                idxout[(size_t)k * NTOK + base + PAIRS + p] = (float)gi1;
            }
        }
        __syncthreads();

        // ---- residual update: RP[d][p] -= code (exact fma(-1,c,r)) ----
        {
            int2 ch = CHO[pq];
            const float4* ca = (const float4*)(cbk + (size_t)ch.x * D) + qh * 8;
            const float4* cw = (const float4*)(cbk + (size_t)ch.y * D) + qh * 8;
            #pragma unroll
            for (int i = 0; i < 8; i++) {
                float4 u = ca[i], w = cw[i];
                int d = qh * 32 + i * 4;
                RP[(d+0)*PAIRS+pq] = fma2(pk2(u.x, w.x), NEG1, RP[(d+0)*PAIRS+pq]);
                RP[(d+1)*PAIRS+pq] = fma2(pk2(u.y, w.y), NEG1, RP[(d+1)*PAIRS+pq]);
                RP[(d+2)*PAIRS+pq] = fma2(pk2(u.z, w.z), NEG1, RP[(d+2)*PAIRS+pq]);
                RP[(d+3)*PAIRS+pq] = fma2(pk2(u.w, w.w), NEG1, RP[(d+3)*PAIRS+pq]);
            }
        }
        __syncthreads();
    }

    // ---- output: quantized = x - residual (exact elementwise) ----
    {
        const float4* xa = (const float4*)(x + (size_t)tok0 * D) + qh * 8;
        const float4* xb = (const float4*)(x + (size_t)tok1 * D) + qh * 8;
        float4* qa = (float4*)(qout + (size_t)tok0 * D) + qh * 8;
        float4* qb = (float4*)(qout + (size_t)tok1 * D) + qh * 8;
        #pragma unroll
        for (int i = 0; i < 8; i++) {
            float4 a = xa[i], b = xb[i];
            float4 oa, ob; float lo, hi;
            int d = qh * 32 + i * 4;
            up2(RP[(d+0)*PAIRS+pq], lo, hi); oa.x = a.x - lo; ob.x = b.x - hi;
            up2(RP[(d+1)*PAIRS+pq], lo, hi); oa.y = a.y - lo; ob.y = b.y - hi;
            up2(RP[(d+2)*PAIRS+pq], lo, hi); oa.z = a.z - lo; ob.z = b.z - hi;
            up2(RP[(d+3)*PAIRS+pq], lo, hi); oa.w = a.w - lo; ob.w = b.w - hi;
            qa[i] = oa; qb[i] = ob;
        }
    }
}

extern "C" void kernel_launch(void* const* d_in, const int* in_sizes, int n_in,
                              void* d_out, int out_size)
{
    const float* x  = (const float*)d_in[0];
    const float* cb = (const float*)d_in[1];
    if (n_in >= 2 && in_sizes[0] == K * M * D && in_sizes[1] == NTOK * D) {
        x  = (const float*)d_in[1];
        cb = (const float*)d_in[0];
    }
    float* q = (float*)d_out;
    float* idxf = (out_size >= NTOK * D + K * NTOK) ? (q + (size_t)NTOK * D) : nullptr;

    cudaFuncSetAttribute(rvq_kernel, cudaFuncAttributeMaxDynamicSharedMemorySize, SMEMB);
    rvq_kernel<<<NCTA, NT, SMEMB>>>(x, cb, q, idxf);
}